// round 7
// baseline (speedup 1.0000x reference)
#include <cuda_runtime.h>
#include <cstdint>

#define C_DIM 256
#define N_TOK 8
#define D_DIM 512
#define HW    4096
#define B_SZ  4
#define EPS   1e-6f

// ---- persistent scratch ----
__device__ float g_sgp[16][B_SZ * C_DIM];
__device__ float g_sg[B_SZ * C_DIM];
__device__ float g_wovp[16][C_DIM * C_DIM];
__device__ float g_wovgT[C_DIM * C_DIM];             // [ch][co]
__device__ float g_agg[(size_t)B_SZ * C_DIM * HW];   // 16MB

#define FMA2(d, a, b, c) \
    asm("fma.rn.f32x2 %0, %1, %2, %3;" : "=l"(d) : "l"(a), "l"(b), "l"(c))
#define DUP2(d, x) \
    asm("mov.b64 %0, {%1, %1};" : "=l"(d) : "r"(__float_as_uint(x)))

// ---------------------------------------------------------------------------
// k_sg2: per (b, 32-d chunk): recompute qp for own chunk, then partial sg.
// ---------------------------------------------------------------------------
__global__ void k_sg2(const float* __restrict__ q, const float* __restrict__ Wq,
                      const float* __restrict__ Wkv) {
    int b = blockIdx.x, ck = blockIdx.y, tid = threadIdx.x;
    __shared__ float qs[C_DIM];
    __shared__ float qps[32];
    qs[tid] = q[b * C_DIM + tid];
    __syncthreads();
    {   // qp for 32 d rows: 8 lanes per d
        int dl = tid >> 3, s = tid & 7;
        const float* wq = Wq + (size_t)(ck * 32 + dl) * C_DIM + s * 32;
        float a = 0.f;
        #pragma unroll
        for (int k = 0; k < 32; ++k) a += __ldg(wq + k) * qs[s * 32 + k];
        a += __shfl_xor_sync(0xffffffffu, a, 1);
        a += __shfl_xor_sync(0xffffffffu, a, 2);
        a += __shfl_xor_sync(0xffffffffu, a, 4);
        if (s == 0) qps[dl] = a;
    }
    __syncthreads();
    float a = 0.f;
    const float* wk = Wkv + (size_t)(ck * 32) * C_DIM + tid;
    #pragma unroll
    for (int d = 0; d < 32; ++d) a += __ldg(wk + (size_t)d * C_DIM) * qps[d];
    g_sgp[ck][b * C_DIM + tid] = a;
}

__global__ void k_sgr(const float* __restrict__ g) {
    int b = blockIdx.x, tid = threadIdx.x;
    float s = 0.f;
    #pragma unroll
    for (int i = 0; i < 16; ++i) s += g_sgp[i][b * C_DIM + tid];
    g_sg[b * C_DIM + tid] = s * g[tid] * rsqrtf((float)D_DIM);
}

__global__ void k_wovp(const float* __restrict__ Wo, const float* __restrict__ Wkv) {
    int co0 = blockIdx.x * 4, kc = blockIdx.y;
    __shared__ float wo_s[4][32];
    int tid = threadIdx.x;
    if (tid < 128) {
        int r = tid >> 5, cc = tid & 31;
        wo_s[r][cc] = __ldg(&Wo[(co0 + r) * D_DIM + kc * 32 + cc]);
    }
    __syncthreads();
    const float* wv = Wkv + (size_t)(D_DIM + kc * 32) * C_DIM + tid;
    float a0 = 0.f, a1 = 0.f, a2 = 0.f, a3 = 0.f;
    #pragma unroll
    for (int d = 0; d < 32; ++d) {
        float v = __ldg(wv + (size_t)d * C_DIM);
        a0 += wo_s[0][d] * v; a1 += wo_s[1][d] * v;
        a2 += wo_s[2][d] * v; a3 += wo_s[3][d] * v;
    }
    float* o = &g_wovp[kc][tid * C_DIM + co0];
    o[0] = a0; o[1] = a1; o[2] = a2; o[3] = a3;
}

__global__ void k_wovr(const float* __restrict__ g) {
    int idx = blockIdx.x * 256 + threadIdx.x;
    float s = 0.f;
    #pragma unroll
    for (int i = 0; i < 16; ++i) s += g_wovp[i][idx];
    g_wovgT[idx] = s * g[idx >> 8];
}

// ---------------------------------------------------------------------------
// k_fuse v3: 16-pixel tiles + occupancy capped at 2 blocks/SM (dummy dyn smem)
// so a tile's lines survive in L2 between phase A and phase B.
// ---------------------------------------------------------------------------
#define FUSE_DYN (100 * 1024)
__global__ void __launch_bounds__(256) k_fuse(const float* __restrict__ c) {
    extern __shared__ float occupancy_cap[];  (void)occupancy_cap;
    __shared__ float dots[N_TOK][16];
    __shared__ float invs[N_TOK][16];
    __shared__ float wgt[N_TOK][16];
    __shared__ float sg_s[C_DIM];

    int tid = threadIdx.x, blk = blockIdx.x;
    int b = blk >> 8;                      // 256 blocks per batch
    int p0 = (blk & 255) * 16;

    sg_s[tid] = g_sg[b * C_DIM + tid];
    __syncthreads();

    const float* cb = c + (size_t)b * N_TOK * C_DIM * HW;

    // ---- Phase A: warp = token n; lane = (p 0..15, ch-half h) ----
    {
        int n = tid >> 5, l = tid & 31;
        int p = l & 15, h = l >> 4;
        const float* base = cb + (size_t)n * C_DIM * HW + (size_t)(h * 128) * HW + p0 + p;
        const float* sgh = sg_s + h * 128;
        float ss = 0.f, dt = 0.f;
        #pragma unroll 16
        for (int ch = 0; ch < 128; ++ch) {
            float v = __ldg(base + (size_t)ch * HW);
            ss += v * v;
            dt += v * sgh[ch];
        }
        ss += __shfl_xor_sync(0xffffffffu, ss, 16);
        dt += __shfl_xor_sync(0xffffffffu, dt, 16);
        if (h == 0) {
            float inv = rsqrtf(ss * (1.0f / C_DIM) + EPS);
            dots[n][p] = dt * inv;
            invs[n][p] = inv;
        }
    }
    __syncthreads();
    if (tid < 128) {
        int n = tid >> 4, p = tid & 15;
        float m = dots[0][p];
        #pragma unroll
        for (int i = 1; i < N_TOK; ++i) m = fmaxf(m, dots[i][p]);
        float sum = 0.f;
        #pragma unroll
        for (int i = 0; i < N_TOK; ++i) sum += __expf(dots[i][p] - m);
        wgt[n][p] = __expf(dots[n][p] - m) / sum * invs[n][p];
    }
    __syncthreads();

    // ---- Phase B: thread = (4-ch group, 4-px group); tile now L2-hot ----
    {
        int p4 = tid & 3, chg = tid >> 2;
        int ch0 = chg * 4, pfl = p4 * 4;
        float4 acc[4];
        #pragma unroll
        for (int j = 0; j < 4; ++j) acc[j] = make_float4(0.f, 0.f, 0.f, 0.f);
        #pragma unroll
        for (int n = 0; n < N_TOK; ++n) {
            float4 w4 = *(const float4*)&wgt[n][pfl];
            const float* rn = cb + (size_t)(n * C_DIM + ch0) * HW + p0 + pfl;
            #pragma unroll
            for (int j = 0; j < 4; ++j) {
                float4 v = __ldg((const float4*)(rn + (size_t)j * HW));
                acc[j].x += w4.x * v.x; acc[j].y += w4.y * v.y;
                acc[j].z += w4.z * v.z; acc[j].w += w4.w * v.w;
            }
        }
        float* ag = g_agg + (size_t)(b * C_DIM + ch0) * HW + p0 + pfl;
        #pragma unroll
        for (int j = 0; j < 4; ++j)
            *(float4*)(ag + (size_t)j * HW) = acc[j];
    }
}

// ---------------------------------------------------------------------------
// k_gemm v2: block = 128co x 128p; FMA2 pairs over CO (weights are natural
// adjacent-float pairs — no dup). Per warp-ch: 2 LDS.32 + 8 LDS.128 + 32 FMA2
// => FMA-bound. Double-buffered staging in dynamic smem.
// ---------------------------------------------------------------------------
#define TP  128
#define TCO 128
#define KC  32
#define GEMM_SMEM (2 * KC * TP * 4 + 2 * KC * TCO * 4)   // 64KB
__global__ void __launch_bounds__(256) k_gemm(const float* __restrict__ bo,
                                              float* __restrict__ out) {
    extern __shared__ float sh[];
    float* aggS = sh;                    // [2][KC][TP]
    float* wovS = sh + 2 * KC * TP;      // [2][KC][TCO]

    int tid = threadIdx.x;
    int blk = blockIdx.x;                // 4b x 2ct x 32pt = 256
    int pt = blk & 31, ct = (blk >> 5) & 1, b = blk >> 6;
    int p0 = pt * TP, co0 = ct * TCO;
    int w = tid >> 5, l = tid & 31;
    int cow = w >> 1, pw = w & 1;        // 4 co-groups(32co) x 2 p-groups(64p)
    int lpa = pw * 64 + l;               // thread's p (and +32)

    unsigned long long acc[16][2];
    #pragma unroll
    for (int i = 0; i < 16; ++i) { acc[i][0] = 0ull; acc[i][1] = 0ull; }

    const float* aggB = g_agg + (size_t)b * C_DIM * HW + p0;

    #define STAGE(BUF, CH0) do {                                                   \
        _Pragma("unroll")                                                          \
        for (int k = 0; k < 4; ++k) {                                              \
            int idx = tid + k * 256;                                               \
            int ch = idx >> 5, f = idx & 31;                                       \
            *(float4*)&aggS[((BUF) * KC + ch) * TP + f * 4] =                      \
                __ldg((const float4*)(aggB + (size_t)((CH0) + ch) * HW) + f);      \
        }                                                                          \
        _Pragma("unroll")                                                          \
        for (int k = 0; k < 4; ++k) {                                              \
            int idx = tid + k * 256;                                               \
            int ch = idx >> 5, f = idx & 31;                                       \
            *(float4*)&wovS[((BUF) * KC + ch) * TCO + f * 4] =                     \
                __ldg((const float4*)&g_wovgT[((CH0) + ch) * C_DIM + co0] + f);    \
        }                                                                          \
    } while (0)

    STAGE(0, 0);
    #pragma unroll
    for (int ck = 0; ck < 8; ++ck) {
        __syncthreads();
        if (ck < 7) STAGE((ck + 1) & 1, (ck + 1) * KC);
        int cur = ck & 1;
        #pragma unroll
        for (int ch = 0; ch < KC; ++ch) {
            const float* ar = &aggS[(cur * KC + ch) * TP];
            float a0 = ar[lpa], a1 = ar[lpa + 32];
            unsigned long long ad0, ad1;
            DUP2(ad0, a0); DUP2(ad1, a1);
            const ulonglong2* wp2 =
                (const ulonglong2*)&wovS[(cur * KC + ch) * TCO + cow * 32];
            #pragma unroll
            for (int i = 0; i < 8; ++i) {
                ulonglong2 ww = wp2[i];
                FMA2(acc[2*i  ][0], ww.x, ad0, acc[2*i  ][0]);
                FMA2(acc[2*i  ][1], ww.x, ad1, acc[2*i  ][1]);
                FMA2(acc[2*i+1][0], ww.y, ad0, acc[2*i+1][0]);
                FMA2(acc[2*i+1][1], ww.y, ad1, acc[2*i+1][1]);
            }
        }
    }
    #undef STAGE

    // epilogue: acc[i] = f32x2 over co-pair (2i, 2i+1); [0]=p lpa, [1]=p lpa+32
    float* ob = out + ((size_t)b * C_DIM + co0 + cow * 32) * HW + p0;
    #pragma unroll
    for (int i = 0; i < 16; ++i) {
        int co = cow * 32 + 2 * i;
        float blo = __ldg(&bo[co0 + co]);
        float bhi = __ldg(&bo[co0 + co + 1]);
        unsigned x0, x1, y0, y1;
        asm("mov.b64 {%0, %1}, %2;" : "=r"(x0), "=r"(x1) : "l"(acc[i][0]));
        asm("mov.b64 {%0, %1}, %2;" : "=r"(y0), "=r"(y1) : "l"(acc[i][1]));
        float* r0 = ob + (size_t)(2 * i) * HW;
        float* r1 = r0 + HW;
        r0[lpa]      = __uint_as_float(x0) + blo;
        r0[lpa + 32] = __uint_as_float(y0) + blo;
        r1[lpa]      = __uint_as_float(x1) + bhi;
        r1[lpa + 32] = __uint_as_float(y1) + bhi;
    }
}

extern "C" void kernel_launch(void* const* d_in, const int* in_sizes, int n_in,
                              void* d_out, int out_size) {
    const float* q   = (const float*)d_in[0];
    const float* c   = (const float*)d_in[1];
    const float* g   = (const float*)d_in[2];
    const float* Wq  = (const float*)d_in[3];
    const float* Wkv = (const float*)d_in[4];
    const float* Wo  = (const float*)d_in[5];
    const float* bo  = (const float*)d_in[6];
    float* out = (float*)d_out;

    cudaFuncSetAttribute(k_fuse, cudaFuncAttributeMaxDynamicSharedMemorySize, FUSE_DYN);
    cudaFuncSetAttribute(k_gemm, cudaFuncAttributeMaxDynamicSharedMemorySize, GEMM_SMEM);

    // launch idx 3 = k_fuse (ncu capture slot)
    k_sg2<<<dim3(B_SZ, 16), 256>>>(q, Wq, Wkv);
    k_sgr<<<B_SZ, 256>>>(g);
    k_wovp<<<dim3(64, 16), 256>>>(Wo, Wkv);
    k_fuse<<<B_SZ * (HW / 16), 256, FUSE_DYN>>>(c);
    k_wovr<<<256, 256>>>(g);
    k_gemm<<<256, 256, GEMM_SMEM>>>(bo, out);
}

// round 8
// speedup vs baseline: 1.4878x; 1.4878x over previous
#include <cuda_runtime.h>
#include <cstdint>

#define C_DIM 256
#define N_TOK 8
#define D_DIM 512
#define HW    4096
#define B_SZ  4
#define EPS   1e-6f

// ---- persistent scratch ----
__device__ float g_sgp[16][B_SZ * C_DIM];
__device__ float g_wovgT[C_DIM * C_DIM];             // [ch][co], atomically accumulated
__device__ float g_agg[(size_t)B_SZ * C_DIM * HW];   // 16MB

#define FMA2(d, a, b, c) \
    asm("fma.rn.f32x2 %0, %1, %2, %3;" : "=l"(d) : "l"(a), "l"(b), "l"(c))

// ---------------------------------------------------------------------------
// L0 k_sg2: per (b, 32-d chunk): qp for own chunk, then partial sg.
//           Also zeroes g_wovgT (64 blk x 256 thr x 1 float4 = 64K floats).
// ---------------------------------------------------------------------------
__global__ void k_sg2(const float* __restrict__ q, const float* __restrict__ Wq,
                      const float* __restrict__ Wkv) {
    int b = blockIdx.x, ck = blockIdx.y, tid = threadIdx.x;
    // zero the atomic accumulator (independent of the rest of this kernel)
    ((float4*)g_wovgT)[(b * 16 + ck) * 256 + tid] = make_float4(0.f, 0.f, 0.f, 0.f);

    __shared__ float qs[C_DIM];
    __shared__ float qps[32];
    qs[tid] = q[b * C_DIM + tid];
    __syncthreads();
    {   // qp for 32 d rows: 8 lanes per d
        int dl = tid >> 3, s = tid & 7;
        const float* wq = Wq + (size_t)(ck * 32 + dl) * C_DIM + s * 32;
        float a = 0.f;
        #pragma unroll
        for (int k = 0; k < 32; ++k) a += __ldg(wq + k) * qs[s * 32 + k];
        a += __shfl_xor_sync(0xffffffffu, a, 1);
        a += __shfl_xor_sync(0xffffffffu, a, 2);
        a += __shfl_xor_sync(0xffffffffu, a, 4);
        if (s == 0) qps[dl] = a;
    }
    __syncthreads();
    float a = 0.f;
    const float* wk = Wkv + (size_t)(ck * 32) * C_DIM + tid;
    #pragma unroll
    for (int d = 0; d < 32; ++d) a += __ldg(wk + (size_t)d * C_DIM) * qps[d];
    g_sgp[ck][b * C_DIM + tid] = a;
}

// ---------------------------------------------------------------------------
// L1 k_wovp: partial (g[ch] * sum_{d in chunk} Wo[co,d]*Wv[d,ch]) -> atomicAdd
// ---------------------------------------------------------------------------
__global__ void k_wovp(const float* __restrict__ Wo, const float* __restrict__ Wkv,
                       const float* __restrict__ g) {
    int co0 = blockIdx.x * 4, kc = blockIdx.y;
    __shared__ float wo_s[4][32];
    int tid = threadIdx.x;
    if (tid < 128) {
        int r = tid >> 5, cc = tid & 31;
        wo_s[r][cc] = __ldg(&Wo[(co0 + r) * D_DIM + kc * 32 + cc]);
    }
    __syncthreads();
    const float* wv = Wkv + (size_t)(D_DIM + kc * 32) * C_DIM + tid;
    float a0 = 0.f, a1 = 0.f, a2 = 0.f, a3 = 0.f;
    #pragma unroll
    for (int d = 0; d < 32; ++d) {
        float v = __ldg(wv + (size_t)d * C_DIM);
        a0 += wo_s[0][d] * v; a1 += wo_s[1][d] * v;
        a2 += wo_s[2][d] * v; a3 += wo_s[3][d] * v;
    }
    float gg = g[tid];
    float* o = &g_wovgT[tid * C_DIM + co0];
    atomicAdd(o + 0, a0 * gg);
    atomicAdd(o + 1, a1 * gg);
    atomicAdd(o + 2, a2 * gg);
    atomicAdd(o + 3, a3 * gg);
}

// ---------------------------------------------------------------------------
// L2 k_fuse (R6 form, 50.9us measured): 32-px tiles, no staging, no occ cap.
//    sg reduction inlined (was k_sgr).
// ---------------------------------------------------------------------------
__global__ void __launch_bounds__(256) k_fuse(const float* __restrict__ c,
                                              const float* __restrict__ g) {
    __shared__ float dots[N_TOK][32];
    __shared__ float invs[N_TOK][32];
    __shared__ float wgt[N_TOK][32];
    __shared__ float sg_s[C_DIM];

    int tid = threadIdx.x;
    int blk = blockIdx.x;
    int b = blk >> 7;
    int p0 = (blk & 127) * 32;

    {   // inline sg reduce: sum 16 partials, scale
        float s = 0.f;
        #pragma unroll
        for (int i = 0; i < 16; ++i) s += g_sgp[i][b * C_DIM + tid];
        sg_s[tid] = s * g[tid] * rsqrtf((float)D_DIM);
    }
    __syncthreads();

    const float* cb = c + (size_t)b * N_TOK * C_DIM * HW;

    // ---- Phase A ----
    {
        int n = tid >> 5, p = tid & 31;
        const float* base = cb + (size_t)n * C_DIM * HW + p0 + p;
        float ss = 0.f, dt = 0.f;
        #pragma unroll 4
        for (int ch0 = 0; ch0 < C_DIM; ch0 += 4) {
            float4 s4 = *(const float4*)&sg_s[ch0];
            float v0 = __ldg(base + (size_t)(ch0 + 0) * HW);
            float v1 = __ldg(base + (size_t)(ch0 + 1) * HW);
            float v2 = __ldg(base + (size_t)(ch0 + 2) * HW);
            float v3 = __ldg(base + (size_t)(ch0 + 3) * HW);
            ss += v0 * v0 + v1 * v1 + v2 * v2 + v3 * v3;
            dt += v0 * s4.x + v1 * s4.y + v2 * s4.z + v3 * s4.w;
        }
        float inv = rsqrtf(ss * (1.0f / C_DIM) + EPS);
        dots[n][p] = dt * inv;
        invs[n][p] = inv;
    }
    __syncthreads();

    {
        int n = tid >> 5, p = tid & 31;
        float m = dots[0][p];
        #pragma unroll
        for (int i = 1; i < N_TOK; ++i) m = fmaxf(m, dots[i][p]);
        float sum = 0.f;
        #pragma unroll
        for (int i = 0; i < N_TOK; ++i) sum += __expf(dots[i][p] - m);
        wgt[n][p] = __expf(dots[n][p] - m) / sum * invs[n][p];
    }
    __syncthreads();

    // ---- Phase B ----
    {
        int p4 = tid & 7;
        int chg = tid >> 3;
        int ch0 = chg * 8;
        float4 acc[8];
        #pragma unroll
        for (int j = 0; j < 8; ++j) acc[j] = make_float4(0.f, 0.f, 0.f, 0.f);

        #pragma unroll
        for (int n = 0; n < N_TOK; ++n) {
            float4 w4 = *(const float4*)&wgt[n][p4 * 4];
            const float* rn = cb + (size_t)(n * C_DIM + ch0) * HW + p0 + p4 * 4;
            #pragma unroll
            for (int j = 0; j < 8; ++j) {
                float4 v = __ldg((const float4*)(rn + (size_t)j * HW));
                acc[j].x += w4.x * v.x; acc[j].y += w4.y * v.y;
                acc[j].z += w4.z * v.z; acc[j].w += w4.w * v.w;
            }
        }
        float* ag = g_agg + (size_t)(b * C_DIM + ch0) * HW + p0 + p4 * 4;
        #pragma unroll
        for (int j = 0; j < 8; ++j)
            *(float4*)(ag + (size_t)j * HW) = acc[j];
    }
}

// ---------------------------------------------------------------------------
// L3 k_gemm (R6/R4 v1 form — exact): 64co x 128p, K=32 chunks, double-buffered.
//    *** This launch sits in the ncu capture slot (idx 3). ***
// ---------------------------------------------------------------------------
#define TP  128
#define TCO 64
#define KC  32
__global__ void __launch_bounds__(256) k_gemm(const float* __restrict__ bo,
                                              float* __restrict__ out) {
    __shared__ float aggS[2][KC][TP];
    __shared__ unsigned long long wovD[2][KC][TCO];
    int tid = threadIdx.x;
    int blk = blockIdx.x;
    int pt = blk & 31, ct = (blk >> 5) & 3, b = blk >> 7;
    int p0 = pt * TP, co0 = ct * TCO;
    int tx = tid & 31, ty = tid >> 5;
    int po = tx * 4, coo = ty * 8;

    unsigned long long acc[8][2];
    #pragma unroll
    for (int i = 0; i < 8; ++i) { acc[i][0] = 0ull; acc[i][1] = 0ull; }

    const float* aggB = g_agg + (size_t)b * C_DIM * HW + p0;

    #define STAGE(BUF, CH0) do {                                               \
        _Pragma("unroll")                                                      \
        for (int k = 0; k < 4; ++k) {                                          \
            int idx = tid + k * 256;                                           \
            int ch = idx >> 5, f = idx & 31;                                   \
            *(float4*)&aggS[BUF][ch][f * 4] =                                  \
                __ldg((const float4*)(aggB + (size_t)((CH0) + ch) * HW) + f);  \
        }                                                                      \
        _Pragma("unroll")                                                      \
        for (int k = 0; k < 8; ++k) {                                          \
            int idx = tid + k * 256;                                           \
            int ch = idx >> 6, co = idx & 63;                                  \
            float w = __ldg(&g_wovgT[((CH0) + ch) * C_DIM + co0 + co]);        \
            unsigned long long pk;                                             \
            asm("mov.b64 %0, {%1, %1};" : "=l"(pk) : "r"(__float_as_uint(w))); \
            wovD[BUF][ch][co] = pk;                                            \
        }                                                                      \
    } while (0)

    STAGE(0, 0);
    #pragma unroll
    for (int ck = 0; ck < 8; ++ck) {
        __syncthreads();
        if (ck < 7) STAGE((ck + 1) & 1, (ck + 1) * KC);
        int cur = ck & 1;
        #pragma unroll
        for (int ch = 0; ch < KC; ++ch) {
            ulonglong2 ap = *(const ulonglong2*)&aggS[cur][ch][po];
            const unsigned long long* wp = &wovD[cur][ch][coo];
            #pragma unroll
            for (int i = 0; i < 8; ++i) {
                FMA2(acc[i][0], wp[i], ap.x, acc[i][0]);
                FMA2(acc[i][1], wp[i], ap.y, acc[i][1]);
            }
        }
    }
    #undef STAGE

    float* ob = out + ((size_t)b * C_DIM + co0 + coo) * HW + p0 + po;
    #pragma unroll
    for (int i = 0; i < 8; ++i) {
        float bb = __ldg(&bo[co0 + coo + i]);
        unsigned lx, ly, hx, hy;
        asm("mov.b64 {%0, %1}, %2;" : "=r"(lx), "=r"(ly) : "l"(acc[i][0]));
        asm("mov.b64 {%0, %1}, %2;" : "=r"(hx), "=r"(hy) : "l"(acc[i][1]));
        float4 r = make_float4(__uint_as_float(lx) + bb, __uint_as_float(ly) + bb,
                               __uint_as_float(hx) + bb, __uint_as_float(hy) + bb);
        *(float4*)(ob + (size_t)i * HW) = r;
    }
}

extern "C" void kernel_launch(void* const* d_in, const int* in_sizes, int n_in,
                              void* d_out, int out_size) {
    const float* q   = (const float*)d_in[0];
    const float* c   = (const float*)d_in[1];
    const float* g   = (const float*)d_in[2];
    const float* Wq  = (const float*)d_in[3];
    const float* Wkv = (const float*)d_in[4];
    const float* Wo  = (const float*)d_in[5];
    const float* bo  = (const float*)d_in[6];
    float* out = (float*)d_out;

    // Exactly 4 launches; ncu capture slot (idx 3) = k_gemm.
    k_sg2<<<dim3(B_SZ, 16), 256>>>(q, Wq, Wkv);     // also zeroes g_wovgT
    k_wovp<<<dim3(64, 16), 256>>>(Wo, Wkv, g);      // atomic accumulate (x g)
    k_fuse<<<B_SZ * (HW / 32), 256>>>(c, g);        // inline sg reduce
    k_gemm<<<512, 256>>>(bo, out);
}

// round 9
// speedup vs baseline: 1.6630x; 1.1178x over previous
#include <cuda_runtime.h>
#include <cstdint>

#define C_DIM 256
#define N_TOK 8
#define D_DIM 512
#define HW    4096
#define B_SZ  4
#define EPS   1e-6f

// ---- persistent scratch ----
__device__ float g_sgp[16][B_SZ * C_DIM];
__device__ float g_wovgT[C_DIM * C_DIM];             // [ch][co], atomically accumulated
__device__ float g_agg[(size_t)B_SZ * C_DIM * HW];   // 16MB

#define FMA2(d, a, b, c) \
    asm("fma.rn.f32x2 %0, %1, %2, %3;" : "=l"(d) : "l"(a), "l"(b), "l"(c))
#define DUP2(d, x) \
    asm("mov.b64 %0, {%1, %1};" : "=l"(d) : "r"(__float_as_uint(x)))

// ---------------------------------------------------------------------------
// L0 k_sg2: per (b, 32-d chunk): qp for own chunk, then partial sg.
//           Also zeroes g_wovgT.
// ---------------------------------------------------------------------------
__global__ void k_sg2(const float* __restrict__ q, const float* __restrict__ Wq,
                      const float* __restrict__ Wkv) {
    int b = blockIdx.x, ck = blockIdx.y, tid = threadIdx.x;
    ((float4*)g_wovgT)[(b * 16 + ck) * 256 + tid] = make_float4(0.f, 0.f, 0.f, 0.f);

    __shared__ float qs[C_DIM];
    __shared__ float qps[32];
    qs[tid] = q[b * C_DIM + tid];
    __syncthreads();
    {
        int dl = tid >> 3, s = tid & 7;
        const float* wq = Wq + (size_t)(ck * 32 + dl) * C_DIM + s * 32;
        float a = 0.f;
        #pragma unroll
        for (int k = 0; k < 32; ++k) a += __ldg(wq + k) * qs[s * 32 + k];
        a += __shfl_xor_sync(0xffffffffu, a, 1);
        a += __shfl_xor_sync(0xffffffffu, a, 2);
        a += __shfl_xor_sync(0xffffffffu, a, 4);
        if (s == 0) qps[dl] = a;
    }
    __syncthreads();
    float a = 0.f;
    const float* wk = Wkv + (size_t)(ck * 32) * C_DIM + tid;
    #pragma unroll
    for (int d = 0; d < 32; ++d) a += __ldg(wk + (size_t)d * C_DIM) * qps[d];
    g_sgp[ck][b * C_DIM + tid] = a;
}

// ---------------------------------------------------------------------------
// L1 k_wovp: partial (g[ch] * sum_{d in chunk} Wo[co,d]*Wv[d,ch]) -> atomicAdd
// ---------------------------------------------------------------------------
__global__ void k_wovp(const float* __restrict__ Wo, const float* __restrict__ Wkv,
                       const float* __restrict__ g) {
    int co0 = blockIdx.x * 4, kc = blockIdx.y;
    __shared__ float wo_s[4][32];
    int tid = threadIdx.x;
    if (tid < 128) {
        int r = tid >> 5, cc = tid & 31;
        wo_s[r][cc] = __ldg(&Wo[(co0 + r) * D_DIM + kc * 32 + cc]);
    }
    __syncthreads();
    const float* wv = Wkv + (size_t)(D_DIM + kc * 32) * C_DIM + tid;
    float a0 = 0.f, a1 = 0.f, a2 = 0.f, a3 = 0.f;
    #pragma unroll
    for (int d = 0; d < 32; ++d) {
        float v = __ldg(wv + (size_t)d * C_DIM);
        a0 += wo_s[0][d] * v; a1 += wo_s[1][d] * v;
        a2 += wo_s[2][d] * v; a3 += wo_s[3][d] * v;
    }
    float gg = g[tid];
    float* o = &g_wovgT[tid * C_DIM + co0];
    atomicAdd(o + 0, a0 * gg);
    atomicAdd(o + 1, a1 * gg);
    atomicAdd(o + 2, a2 * gg);
    atomicAdd(o + 3, a3 * gg);
}

// ---------------------------------------------------------------------------
// L2 k_fuse (R6 form, 50.9us measured — unchanged)
// ---------------------------------------------------------------------------
__global__ void __launch_bounds__(256) k_fuse(const float* __restrict__ c,
                                              const float* __restrict__ g) {
    __shared__ float dots[N_TOK][32];
    __shared__ float invs[N_TOK][32];
    __shared__ float wgt[N_TOK][32];
    __shared__ float sg_s[C_DIM];

    int tid = threadIdx.x;
    int blk = blockIdx.x;
    int b = blk >> 7;
    int p0 = (blk & 127) * 32;

    {
        float s = 0.f;
        #pragma unroll
        for (int i = 0; i < 16; ++i) s += g_sgp[i][b * C_DIM + tid];
        sg_s[tid] = s * g[tid] * rsqrtf((float)D_DIM);
    }
    __syncthreads();

    const float* cb = c + (size_t)b * N_TOK * C_DIM * HW;

    {
        int n = tid >> 5, p = tid & 31;
        const float* base = cb + (size_t)n * C_DIM * HW + p0 + p;
        float ss = 0.f, dt = 0.f;
        #pragma unroll 4
        for (int ch0 = 0; ch0 < C_DIM; ch0 += 4) {
            float4 s4 = *(const float4*)&sg_s[ch0];
            float v0 = __ldg(base + (size_t)(ch0 + 0) * HW);
            float v1 = __ldg(base + (size_t)(ch0 + 1) * HW);
            float v2 = __ldg(base + (size_t)(ch0 + 2) * HW);
            float v3 = __ldg(base + (size_t)(ch0 + 3) * HW);
            ss += v0 * v0 + v1 * v1 + v2 * v2 + v3 * v3;
            dt += v0 * s4.x + v1 * s4.y + v2 * s4.z + v3 * s4.w;
        }
        float inv = rsqrtf(ss * (1.0f / C_DIM) + EPS);
        dots[n][p] = dt * inv;
        invs[n][p] = inv;
    }
    __syncthreads();

    {
        int n = tid >> 5, p = tid & 31;
        float m = dots[0][p];
        #pragma unroll
        for (int i = 1; i < N_TOK; ++i) m = fmaxf(m, dots[i][p]);
        float sum = 0.f;
        #pragma unroll
        for (int i = 0; i < N_TOK; ++i) sum += __expf(dots[i][p] - m);
        wgt[n][p] = __expf(dots[n][p] - m) / sum * invs[n][p];
    }
    __syncthreads();

    {
        int p4 = tid & 7;
        int chg = tid >> 3;
        int ch0 = chg * 8;
        float4 acc[8];
        #pragma unroll
        for (int j = 0; j < 8; ++j) acc[j] = make_float4(0.f, 0.f, 0.f, 0.f);

        #pragma unroll
        for (int n = 0; n < N_TOK; ++n) {
            float4 w4 = *(const float4*)&wgt[n][p4 * 4];
            const float* rn = cb + (size_t)(n * C_DIM + ch0) * HW + p0 + p4 * 4;
            #pragma unroll
            for (int j = 0; j < 8; ++j) {
                float4 v = __ldg((const float4*)(rn + (size_t)j * HW));
                acc[j].x += w4.x * v.x; acc[j].y += w4.y * v.y;
                acc[j].z += w4.z * v.z; acc[j].w += w4.w * v.w;
            }
        }
        float* ag = g_agg + (size_t)(b * C_DIM + ch0) * HW + p0 + p4 * 4;
        #pragma unroll
        for (int j = 0; j < 8; ++j)
            *(float4*)(ag + (size_t)j * HW) = acc[j];
    }
}

// ---------------------------------------------------------------------------
// L3 k_gemm v3: identical structure to R8 (grid 512, 64co x 128p, K=32,
// double-buffer), but inner loop pairs FMA2 over CO:
//   weights stored raw (no dup), read as 2x LDS.128 broadcast  -> 2 wf
//   agg LDS.128 (4p) + 4 DUP2 on alu pipe                      -> 4 wf
//   per warp-ch: 6 wf (was 12) vs 64 FMA-issue cyc -> FMA-bound.
// ---------------------------------------------------------------------------
#define TP  128
#define TCO 64
#define KC  32
__global__ void __launch_bounds__(256) k_gemm(const float* __restrict__ bo,
                                              float* __restrict__ out) {
    __shared__ float aggS[2][KC][TP];        // 32KB
    __shared__ float wovS[2][KC][TCO];       // 16KB
    int tid = threadIdx.x;
    int blk = blockIdx.x;
    int pt = blk & 31, ct = (blk >> 5) & 3, b = blk >> 7;
    int p0 = pt * TP, co0 = ct * TCO;
    int tx = tid & 31, ty = tid >> 5;
    int po = tx * 4, coo = ty * 8;           // 8 co = 4 natural f32x2 pairs

    unsigned long long acc[4][4];            // [co-pair][p]
    #pragma unroll
    for (int i = 0; i < 4; ++i)
        #pragma unroll
        for (int j = 0; j < 4; ++j) acc[i][j] = 0ull;

    const float* aggB = g_agg + (size_t)b * C_DIM * HW + p0;

    #define STAGE(BUF, CH0) do {                                               \
        _Pragma("unroll")                                                      \
        for (int k = 0; k < 4; ++k) {                                          \
            int idx = tid + k * 256;                                           \
            int ch = idx >> 5, f = idx & 31;                                   \
            *(float4*)&aggS[BUF][ch][f * 4] =                                  \
                __ldg((const float4*)(aggB + (size_t)((CH0) + ch) * HW) + f);  \
        }                                                                      \
        _Pragma("unroll")                                                      \
        for (int k = 0; k < 2; ++k) {                                          \
            int idx = tid + k * 256;                                           \
            int ch = idx >> 4, f = idx & 15;                                   \
            *(float4*)&wovS[BUF][ch][f * 4] =                                  \
                __ldg((const float4*)&g_wovgT[((CH0) + ch) * C_DIM + co0] + f);\
        }                                                                      \
    } while (0)

    STAGE(0, 0);
    #pragma unroll
    for (int ck = 0; ck < 8; ++ck) {
        __syncthreads();
        if (ck < 7) STAGE((ck + 1) & 1, (ck + 1) * KC);
        int cur = ck & 1;
        #pragma unroll
        for (int ch = 0; ch < KC; ++ch) {
            float4 a4 = *(const float4*)&aggS[cur][ch][po];
            unsigned long long ad0, ad1, ad2, ad3;
            DUP2(ad0, a4.x); DUP2(ad1, a4.y); DUP2(ad2, a4.z); DUP2(ad3, a4.w);
            const ulonglong2* wp2 = (const ulonglong2*)&wovS[cur][ch][coo];
            ulonglong2 w01 = wp2[0], w23 = wp2[1];   // 4 co-pairs
            FMA2(acc[0][0], w01.x, ad0, acc[0][0]); FMA2(acc[0][1], w01.x, ad1, acc[0][1]);
            FMA2(acc[0][2], w01.x, ad2, acc[0][2]); FMA2(acc[0][3], w01.x, ad3, acc[0][3]);
            FMA2(acc[1][0], w01.y, ad0, acc[1][0]); FMA2(acc[1][1], w01.y, ad1, acc[1][1]);
            FMA2(acc[1][2], w01.y, ad2, acc[1][2]); FMA2(acc[1][3], w01.y, ad3, acc[1][3]);
            FMA2(acc[2][0], w23.x, ad0, acc[2][0]); FMA2(acc[2][1], w23.x, ad1, acc[2][1]);
            FMA2(acc[2][2], w23.x, ad2, acc[2][2]); FMA2(acc[2][3], w23.x, ad3, acc[2][3]);
            FMA2(acc[3][0], w23.y, ad0, acc[3][0]); FMA2(acc[3][1], w23.y, ad1, acc[3][1]);
            FMA2(acc[3][2], w23.y, ad2, acc[3][2]); FMA2(acc[3][3], w23.y, ad3, acc[3][3]);
        }
    }
    #undef STAGE

    // acc[k][j] = (co = coo+2k -> lo, co = coo+2k+1 -> hi) at pixel po+j
    float* ob = out + ((size_t)b * C_DIM + co0 + coo) * HW + p0 + po;
    #pragma unroll
    for (int k = 0; k < 4; ++k) {
        float blo = __ldg(&bo[co0 + coo + 2 * k]);
        float bhi = __ldg(&bo[co0 + coo + 2 * k + 1]);
        unsigned lo[4], hi[4];
        #pragma unroll
        for (int j = 0; j < 4; ++j)
            asm("mov.b64 {%0, %1}, %2;" : "=r"(lo[j]), "=r"(hi[j]) : "l"(acc[k][j]));
        float4 rlo = make_float4(__uint_as_float(lo[0]) + blo, __uint_as_float(lo[1]) + blo,
                                 __uint_as_float(lo[2]) + blo, __uint_as_float(lo[3]) + blo);
        float4 rhi = make_float4(__uint_as_float(hi[0]) + bhi, __uint_as_float(hi[1]) + bhi,
                                 __uint_as_float(hi[2]) + bhi, __uint_as_float(hi[3]) + bhi);
        *(float4*)(ob + (size_t)(2 * k) * HW)     = rlo;
        *(float4*)(ob + (size_t)(2 * k + 1) * HW) = rhi;
    }
}

extern "C" void kernel_launch(void* const* d_in, const int* in_sizes, int n_in,
                              void* d_out, int out_size) {
    const float* q   = (const float*)d_in[0];
    const float* c   = (const float*)d_in[1];
    const float* g   = (const float*)d_in[2];
    const float* Wq  = (const float*)d_in[3];
    const float* Wkv = (const float*)d_in[4];
    const float* Wo  = (const float*)d_in[5];
    const float* bo  = (const float*)d_in[6];
    float* out = (float*)d_out;

    // 4 launches; ncu capture slot (idx 3) = k_gemm.
    k_sg2<<<dim3(B_SZ, 16), 256>>>(q, Wq, Wkv);
    k_wovp<<<dim3(64, 16), 256>>>(Wo, Wkv, g);
    k_fuse<<<B_SZ * (HW / 32), 256>>>(c, g);
    k_gemm<<<512, 256>>>(bo, out);
}

// round 11
// speedup vs baseline: 1.8479x; 1.1112x over previous
#include <cuda_runtime.h>
#include <cstdint>

#define C_DIM 256
#define N_TOK 8
#define D_DIM 512
#define HW    4096
#define B_SZ  4
#define EPS   1e-6f

// ---- persistent scratch ----
__device__ float g_sgp[16][B_SZ * C_DIM];
__device__ float g_wovgT[C_DIM * C_DIM];             // [ch][co], atomically accumulated

#define FMA2(d, a, b, c) \
    asm("fma.rn.f32x2 %0, %1, %2, %3;" : "=l"(d) : "l"(a), "l"(b), "l"(c))
#define DUP2(d, x) \
    asm("mov.b64 %0, {%1, %1};" : "=l"(d) : "r"(__float_as_uint(x)))

// ---------------------------------------------------------------------------
// L0 k_sg2: per (b, 32-d chunk): qp for own chunk, then partial sg.
//           Also zeroes g_wovgT.
// ---------------------------------------------------------------------------
__global__ void k_sg2(const float* __restrict__ q, const float* __restrict__ Wq,
                      const float* __restrict__ Wkv) {
    int b = blockIdx.x, ck = blockIdx.y, tid = threadIdx.x;
    ((float4*)g_wovgT)[(b * 16 + ck) * 256 + tid] = make_float4(0.f, 0.f, 0.f, 0.f);

    __shared__ float qs[C_DIM];
    __shared__ float qps[32];
    qs[tid] = q[b * C_DIM + tid];
    __syncthreads();
    {
        int dl = tid >> 3, s = tid & 7;
        const float* wq = Wq + (size_t)(ck * 32 + dl) * C_DIM + s * 32;
        float a = 0.f;
        #pragma unroll
        for (int k = 0; k < 32; ++k) a += __ldg(wq + k) * qs[s * 32 + k];
        a += __shfl_xor_sync(0xffffffffu, a, 1);
        a += __shfl_xor_sync(0xffffffffu, a, 2);
        a += __shfl_xor_sync(0xffffffffu, a, 4);
        if (s == 0) qps[dl] = a;
    }
    __syncthreads();
    float a = 0.f;
    const float* wk = Wkv + (size_t)(ck * 32) * C_DIM + tid;
    #pragma unroll
    for (int d = 0; d < 32; ++d) a += __ldg(wk + (size_t)d * C_DIM) * qps[d];
    g_sgp[ck][b * C_DIM + tid] = a;
}

// ---------------------------------------------------------------------------
// L1 k_wovp: partial (g[ch] * sum_{d in chunk} Wo[co,d]*Wv[d,ch]) -> atomicAdd
// ---------------------------------------------------------------------------
__global__ void k_wovp(const float* __restrict__ Wo, const float* __restrict__ Wkv,
                       const float* __restrict__ g) {
    int co0 = blockIdx.x * 4, kc = blockIdx.y;
    __shared__ float wo_s[4][32];
    int tid = threadIdx.x;
    if (tid < 128) {
        int r = tid >> 5, cc = tid & 31;
        wo_s[r][cc] = __ldg(&Wo[(co0 + r) * D_DIM + kc * 32 + cc]);
    }
    __syncthreads();
    const float* wv = Wkv + (size_t)(D_DIM + kc * 32) * C_DIM + tid;
    float a0 = 0.f, a1 = 0.f, a2 = 0.f, a3 = 0.f;
    #pragma unroll
    for (int d = 0; d < 32; ++d) {
        float v = __ldg(wv + (size_t)d * C_DIM);
        a0 += wo_s[0][d] * v; a1 += wo_s[1][d] * v;
        a2 += wo_s[2][d] * v; a3 += wo_s[3][d] * v;
    }
    float gg = g[tid];
    float* o = &g_wovgT[tid * C_DIM + co0];
    atomicAdd(o + 0, a0 * gg);
    atomicAdd(o + 1, a1 * gg);
    atomicAdd(o + 2, a2 * gg);
    atomicAdd(o + 3, a3 * gg);
}

// ---------------------------------------------------------------------------
// L2 k_main: fused weights+aggregate+GEMM. Block = 32 px of one batch.
//   agg lives in SMEM with stride 36 (144B: 16B-aligned, phase-conflict-free).
// smem: agg[256][36] (36KB) + wov[2][32][256] (64KB) dynamic.
// ---------------------------------------------------------------------------
#define AGG_STRIDE 36
#define MAIN_SMEM (C_DIM * AGG_STRIDE * 4 + 2 * 32 * C_DIM * 4)   // 102400B
__global__ void __launch_bounds__(256, 2) k_main(const float* __restrict__ c,
                                                 const float* __restrict__ g,
                                                 const float* __restrict__ bo,
                                                 float* __restrict__ out) {
    extern __shared__ float sh[];
    float* aggS = sh;                        // [256][36]
    float* wovS = sh + C_DIM * AGG_STRIDE;   // [2][32][256]
    __shared__ float dots[N_TOK][32];
    __shared__ float invs[N_TOK][32];
    __shared__ float wgt[N_TOK][32];
    __shared__ float sg_s[C_DIM];

    int tid = threadIdx.x;
    int blk = blockIdx.x;
    int b = blk >> 7;
    int p0 = (blk & 127) * 32;

    {   // inline sg reduce
        float s = 0.f;
        #pragma unroll
        for (int i = 0; i < 16; ++i) s += g_sgp[i][b * C_DIM + tid];
        sg_s[tid] = s * g[tid] * rsqrtf((float)D_DIM);
    }
    __syncthreads();

    const float* cb = c + (size_t)b * N_TOK * C_DIM * HW;

    // ---- Phase A: RMS + dot ----
    {
        int n = tid >> 5, p = tid & 31;
        const float* base = cb + (size_t)n * C_DIM * HW + p0 + p;
        float ss = 0.f, dt = 0.f;
        #pragma unroll 4
        for (int ch0 = 0; ch0 < C_DIM; ch0 += 4) {
            float4 s4 = *(const float4*)&sg_s[ch0];
            float v0 = __ldg(base + (size_t)(ch0 + 0) * HW);
            float v1 = __ldg(base + (size_t)(ch0 + 1) * HW);
            float v2 = __ldg(base + (size_t)(ch0 + 2) * HW);
            float v3 = __ldg(base + (size_t)(ch0 + 3) * HW);
            ss += v0 * v0 + v1 * v1 + v2 * v2 + v3 * v3;
            dt += v0 * s4.x + v1 * s4.y + v2 * s4.z + v3 * s4.w;
        }
        float inv = rsqrtf(ss * (1.0f / C_DIM) + EPS);
        dots[n][p] = dt * inv;
        invs[n][p] = inv;
    }
    __syncthreads();

    // ---- softmax ----
    {
        int n = tid >> 5, p = tid & 31;
        float m = dots[0][p];
        #pragma unroll
        for (int i = 1; i < N_TOK; ++i) m = fmaxf(m, dots[i][p]);
        float sum = 0.f;
        #pragma unroll
        for (int i = 0; i < N_TOK; ++i) sum += __expf(dots[i][p] - m);
        wgt[n][p] = __expf(dots[n][p] - m) / sum * invs[n][p];
    }
    __syncthreads();

    #define STAGE_W(BUF, CH0) do {                                             \
        _Pragma("unroll")                                                      \
        for (int k = 0; k < 8; ++k) {                                          \
            int idx = tid + k * 256;                                           \
            int ch = idx >> 6, f = idx & 63;                                   \
            *(float4*)&wovS[((BUF) * 32 + ch) * C_DIM + f * 4] =               \
                __ldg((const float4*)&g_wovgT[((CH0) + ch) * C_DIM] + f);      \
        }                                                                      \
    } while (0)

    // kick off weight chunk 0 loads; they overlap phase B compute
    STAGE_W(0, 0);

    // ---- Phase B: aggregate over n -> smem agg ----
    {
        int p4 = tid & 7;
        int chg = tid >> 3;
        int ch0 = chg * 8;
        float4 acc[8];
        #pragma unroll
        for (int j = 0; j < 8; ++j) acc[j] = make_float4(0.f, 0.f, 0.f, 0.f);

        #pragma unroll
        for (int n = 0; n < N_TOK; ++n) {
            float4 w4 = *(const float4*)&wgt[n][p4 * 4];
            const float* rn = cb + (size_t)(n * C_DIM + ch0) * HW + p0 + p4 * 4;
            #pragma unroll
            for (int j = 0; j < 8; ++j) {
                float4 v = __ldg((const float4*)(rn + (size_t)j * HW));
                acc[j].x += w4.x * v.x; acc[j].y += w4.y * v.y;
                acc[j].z += w4.z * v.z; acc[j].w += w4.w * v.w;
            }
        }
        #pragma unroll
        for (int j = 0; j < 8; ++j)
            *(float4*)&aggS[(ch0 + j) * AGG_STRIDE + p4 * 4] = acc[j];
    }

    // ---- GEMM: out[co][p] = bo[co] + sum_ch WovgT[ch][co]*agg[ch][p] ----
    {
        int tx = tid & 7, ty = tid >> 3;     // 8 px-groups x 32 co-groups
        int po = tx * 4, coo = ty * 8;       // 4 px, 8 co (4 f32x2 pairs)

        unsigned long long acc[4][4];        // [co-pair][px]
        #pragma unroll
        for (int i = 0; i < 4; ++i)
            #pragma unroll
            for (int j = 0; j < 4; ++j) acc[i][j] = 0ull;

        #pragma unroll
        for (int ck = 0; ck < 8; ++ck) {
            __syncthreads();                 // staging done + (ck==0) agg ready
            if (ck < 7) STAGE_W((ck + 1) & 1, (ck + 1) * 32);
            int cur = ck & 1;
            #pragma unroll
            for (int ch = 0; ch < 32; ++ch) {
                float4 a4 = *(const float4*)&aggS[(ck * 32 + ch) * AGG_STRIDE + po];
                unsigned long long ad0, ad1, ad2, ad3;
                DUP2(ad0, a4.x); DUP2(ad1, a4.y); DUP2(ad2, a4.z); DUP2(ad3, a4.w);
                const ulonglong2* wp2 =
                    (const ulonglong2*)&wovS[(cur * 32 + ch) * C_DIM + coo];
                ulonglong2 w01 = wp2[0], w23 = wp2[1];
                FMA2(acc[0][0], w01.x, ad0, acc[0][0]); FMA2(acc[0][1], w01.x, ad1, acc[0][1]);
                FMA2(acc[0][2], w01.x, ad2, acc[0][2]); FMA2(acc[0][3], w01.x, ad3, acc[0][3]);
                FMA2(acc[1][0], w01.y, ad0, acc[1][0]); FMA2(acc[1][1], w01.y, ad1, acc[1][1]);
                FMA2(acc[1][2], w01.y, ad2, acc[1][2]); FMA2(acc[1][3], w01.y, ad3, acc[1][3]);
                FMA2(acc[2][0], w23.x, ad0, acc[2][0]); FMA2(acc[2][1], w23.x, ad1, acc[2][1]);
                FMA2(acc[2][2], w23.x, ad2, acc[2][2]); FMA2(acc[2][3], w23.x, ad3, acc[2][3]);
                FMA2(acc[3][0], w23.y, ad0, acc[3][0]); FMA2(acc[3][1], w23.y, ad1, acc[3][1]);
                FMA2(acc[3][2], w23.y, ad2, acc[3][2]); FMA2(acc[3][3], w23.y, ad3, acc[3][3]);
            }
        }

        float* ob = out + ((size_t)b * C_DIM + coo) * HW + p0 + po;
        #pragma unroll
        for (int k = 0; k < 4; ++k) {
            float blo = __ldg(&bo[coo + 2 * k]);
            float bhi = __ldg(&bo[coo + 2 * k + 1]);
            unsigned lo[4], hi[4];
            #pragma unroll
            for (int j = 0; j < 4; ++j)
                asm("mov.b64 {%0, %1}, %2;" : "=r"(lo[j]), "=r"(hi[j]) : "l"(acc[k][j]));
            float4 rlo = make_float4(__uint_as_float(lo[0]) + blo, __uint_as_float(lo[1]) + blo,
                                     __uint_as_float(lo[2]) + blo, __uint_as_float(lo[3]) + blo);
            float4 rhi = make_float4(__uint_as_float(hi[0]) + bhi, __uint_as_float(hi[1]) + bhi,
                                     __uint_as_float(hi[2]) + bhi, __uint_as_float(hi[3]) + bhi);
            *(float4*)(ob + (size_t)(2 * k) * HW)     = rlo;
            *(float4*)(ob + (size_t)(2 * k + 1) * HW) = rhi;
        }
    }
    #undef STAGE_W
}

extern "C" void kernel_launch(void* const* d_in, const int* in_sizes, int n_in,
                              void* d_out, int out_size) {
    const float* q   = (const float*)d_in[0];
    const float* c   = (const float*)d_in[1];
    const float* g   = (const float*)d_in[2];
    const float* Wq  = (const float*)d_in[3];
    const float* Wkv = (const float*)d_in[4];
    const float* Wo  = (const float*)d_in[5];
    const float* bo  = (const float*)d_in[6];
    float* out = (float*)d_out;

    cudaFuncSetAttribute(k_main, cudaFuncAttributeMaxDynamicSharedMemorySize, MAIN_SMEM);

    // 3 launches; capture slot (idx 5 mod 3 = 2) = k_main.
    k_sg2<<<dim3(B_SZ, 16), 256>>>(q, Wq, Wkv);
    k_wovp<<<dim3(64, 16), 256>>>(Wo, Wkv, g);
    k_main<<<B_SZ * (HW / 32), 256, MAIN_SMEM>>>(c, g, bo, out);
}